// round 5
// baseline (speedup 1.0000x reference)
#include <cuda_runtime.h>
#include <cuda_bf16.h>
#include <stdint.h>
#include <math.h>

#define BB 2
#define SS 2048
#define EE 1024
#define HH 16
#define DD 64
#define MTOT (BB*SS)

// ---------------------------------------------------------------------------
// Scratch (device globals — no allocation allowed)
// ---------------------------------------------------------------------------
__device__ float g_bias8[HH*SS];
__device__ __nv_bfloat16 g_ahi[MTOT*EE], g_alo[MTOT*EE];       // hs split
__device__ __nv_bfloat16 g_wthi[4u*EE*EE], g_wtlo[4u*EE*EE];   // W^T splits
__device__ __nv_bfloat16 g_chi[MTOT*EE], g_clo[MTOT*EE];       // ctx split
__device__ __nv_bfloat16 g_qhi[BB*HH*SS*DD], g_qlo[BB*HH*SS*DD];   // [b][h][s][d], pre-scaled
__device__ __nv_bfloat16 g_khi[BB*HH*SS*DD], g_klo[BB*HH*SS*DD];   // [b][h][s][d]
__device__ __nv_bfloat16 g_vthi[BB*HH*SS*DD], g_vtlo[BB*HH*SS*DD]; // [b][h][d][s]

// ---------------------------------------------------------------------------
// helpers
// ---------------------------------------------------------------------------
__device__ __forceinline__ uint32_t smem_u32(const void* p) {
    uint32_t r;
    asm("{ .reg .u64 t; cvta.to.shared.u64 t, %1; cvt.u32.u64 %0, t; }"
        : "=r"(r) : "l"(p));
    return r;
}

__device__ __forceinline__ void cp16(uint32_t dst, const void* src) {
    asm volatile("cp.async.cg.shared.global [%0], [%1], 16;"
                 :: "r"(dst), "l"(__cvta_generic_to_global(src)) : "memory");
}

__device__ __forceinline__ void mma_bf16(float* c, const uint32_t* a, const uint32_t* b) {
    asm volatile(
        "mma.sync.aligned.m16n8k16.row.col.f32.bf16.bf16.f32 "
        "{%0,%1,%2,%3}, {%4,%5,%6,%7}, {%8,%9}, {%0,%1,%2,%3};"
        : "+f"(c[0]), "+f"(c[1]), "+f"(c[2]), "+f"(c[3])
        : "r"(a[0]), "r"(a[1]), "r"(a[2]), "r"(a[3]), "r"(b[0]), "r"(b[1]));
}

__device__ __forceinline__ void ldsm_x4(uint32_t* r, uint32_t addr) {
    asm volatile("ldmatrix.sync.aligned.m8n8.x4.shared.b16 {%0,%1,%2,%3}, [%4];"
        : "=r"(r[0]), "=r"(r[1]), "=r"(r[2]), "=r"(r[3]) : "r"(addr));
}

__device__ __forceinline__ uint32_t pack_bf16x2(float a, float b) {
    uint32_t d;
    asm("cvt.rn.bf16x2.f32 %0, %1, %2;" : "=r"(d) : "f"(b), "f"(a));
    return d;
}
__device__ __forceinline__ uint32_t pack_resid(float a, float b, uint32_t hi) {
    float fa = __uint_as_float(hi << 16);
    float fb = __uint_as_float(hi & 0xffff0000u);
    return pack_bf16x2(a - fa, b - fb);
}

// ---------------------------------------------------------------------------
// bias table
// ---------------------------------------------------------------------------
__global__ void bias_kernel(const float* __restrict__ rel_bias) {
    int idx = blockIdx.x * blockDim.x + threadIdx.x;
    if (idx >= HH * SS) return;
    int h = idx / SS;
    int d = idx % SS;
    int bucket;
    if (d < 16) {
        bucket = d;
    } else {
        float t = (logf((float)d * 0.0625f) / 1.3862943611198906f) * 16.0f;
        int lb = 16 + (int)t;
        bucket = lb < 31 ? lb : 31;
    }
    g_bias8[idx] = rel_bias[bucket * HH + h] * 8.0f;
}

// ---------------------------------------------------------------------------
// split fp32 -> bf16 hi/lo for hs
// ---------------------------------------------------------------------------
__global__ void split_kernel(const float* __restrict__ in) {
    int i = blockIdx.x * blockDim.x + threadIdx.x;
    if (i >= MTOT * EE / 4) return;
    float4 v = ((const float4*)in)[i];
    uint32_t h01 = pack_bf16x2(v.x, v.y), h23 = pack_bf16x2(v.z, v.w);
    uint32_t l01 = pack_resid(v.x, v.y, h01), l23 = pack_resid(v.z, v.w, h23);
    ((uint32_t*)g_ahi)[i * 2] = h01;  ((uint32_t*)g_ahi)[i * 2 + 1] = h23;
    ((uint32_t*)g_alo)[i * 2] = l01;  ((uint32_t*)g_alo)[i * 2 + 1] = l23;
}

// ---------------------------------------------------------------------------
// transpose + split weights
// ---------------------------------------------------------------------------
__global__ void wt_split_kernel(const float* __restrict__ W, int widx) {
    __shared__ float t[32][33];
    int n0 = blockIdx.x * 32, k0 = blockIdx.y * 32;
    int tx = threadIdx.x, ty = threadIdx.y;
#pragma unroll
    for (int i = 0; i < 4; i++)
        t[ty + i * 8][tx] = W[(size_t)(k0 + ty + i * 8) * EE + n0 + tx];
    __syncthreads();
    __nv_bfloat16* hi = g_wthi + (size_t)widx * EE * EE;
    __nv_bfloat16* lo = g_wtlo + (size_t)widx * EE * EE;
#pragma unroll
    for (int i = 0; i < 4; i++) {
        int n = n0 + ty + i * 8, k = k0 + tx;
        float v = t[tx][ty + i * 8];
        __nv_bfloat16 h = __float2bfloat16(v);
        __nv_bfloat16 l = __float2bfloat16(v - __bfloat162float(h));
        hi[(size_t)n * EE + k] = h;
        lo[(size_t)n * EE + k] = l;
    }
}

// ---------------------------------------------------------------------------
// mma.sync bf16-split GEMM (ldmatrix fragments)
//   warps: 2m x 4n; warp tile 64m x 32n
// ---------------------------------------------------------------------------
#define BM 128
#define BN 128
#define BKE 32
#define NSTAGE 4
#define RPAD 80
#define TILE_BYTES (128 * RPAD)
#define STAGE_BYTES (2 * TILE_BYTES)
#define GSMEM (NSTAGE * STAGE_BYTES)
#define NITER 96

__global__ __launch_bounds__(256, 1)
void gemm_mma(const float* __restrict__ bias, float* __restrict__ outp, int mode) {
    extern __shared__ char sm[];
    int tid = threadIdx.x;
    int lane = tid & 31, wid = tid >> 5;
    int wm = wid & 1, wn = wid >> 1;           // 2 m-warps x 4 n-warps
    int g = lane >> 2, tg = lane & 3;
    int m0 = blockIdx.y * BM, n0 = blockIdx.x * BN;

    const __nv_bfloat16* Ahi = (mode == 0) ? g_chi : g_ahi;
    const __nv_bfloat16* Alo = (mode == 0) ? g_clo : g_alo;
    int widx = (mode == 0) ? 3 : (mode - 1);
    const __nv_bfloat16* Bhi = g_wthi + (size_t)widx * EE * EE;
    const __nv_bfloat16* Blo = g_wtlo + (size_t)widx * EE * EE;

    float c[4][4][4];
#pragma unroll
    for (int mt = 0; mt < 4; mt++)
#pragma unroll
        for (int nt = 0; nt < 4; nt++)
#pragma unroll
            for (int i = 0; i < 4; i++) c[mt][nt][i] = 0.f;

    uint32_t smbase = smem_u32(sm);
    // ldmatrix lane-address components
    uint32_t a_lrow = ((uint32_t)((lane >> 3) & 1)) * 8 + (lane & 7);   // row add
    uint32_t a_lcol = ((uint32_t)(lane >> 4)) * 16;                     // byte add
    uint32_t b_lrow = lane & 7;
    uint32_t b_lcol = ((uint32_t)(lane >> 3)) * 16;

    auto load_stage = [&](int git, int s) {
        int seg = git >> 5;
        int kb = (git & 31) * BKE;
        const __nv_bfloat16* Aseg = (seg == 2) ? Alo : Ahi;
        const __nv_bfloat16* Bseg = (seg == 1) ? Blo : Bhi;
        uint32_t As = smbase + s * STAGE_BYTES;
        uint32_t Bs = As + TILE_BYTES;
#pragma unroll
        for (int i = 0; i < 2; i++) {
            int ch = tid + i * 256;
            int m = ch >> 2, k16 = ch & 3;
            uint32_t off = m * RPAD + k16 * 16;
            cp16(As + off, Aseg + (size_t)(m0 + m) * EE + kb + k16 * 8);
            cp16(Bs + off, Bseg + (size_t)(n0 + m) * EE + kb + k16 * 8);
        }
    };

#pragma unroll
    for (int p = 0; p < NSTAGE - 1; p++) {
        load_stage(p, p);
        asm volatile("cp.async.commit_group;" ::: "memory");
    }

    for (int git = 0; git < NITER; git++) {
        asm volatile("cp.async.wait_group %0;" :: "n"(NSTAGE - 2) : "memory");
        __syncthreads();

        int nx = git + NSTAGE - 1;
        if (nx < NITER) load_stage(nx, nx & (NSTAGE - 1));
        asm volatile("cp.async.commit_group;" ::: "memory");

        uint32_t As = smbase + (git & (NSTAGE - 1)) * STAGE_BYTES;
        uint32_t Bs = As + TILE_BYTES;

        uint32_t a[4][8];     // [mt][ks*4 + r]
#pragma unroll
        for (int mt = 0; mt < 4; mt++)
#pragma unroll
            for (int ks = 0; ks < 2; ks++)
                ldsm_x4(&a[mt][ks * 4],
                        As + (wm * 64 + mt * 16 + a_lrow) * RPAD + ks * 32 + a_lcol);

        uint32_t b[4][4];     // [nt][ks*2 + r]
#pragma unroll
        for (int nt = 0; nt < 4; nt++)
            ldsm_x4(b[nt], Bs + (wn * 32 + nt * 8 + b_lrow) * RPAD + b_lcol);

#pragma unroll
        for (int ks = 0; ks < 2; ks++)
#pragma unroll
            for (int mt = 0; mt < 4; mt++)
#pragma unroll
                for (int nt = 0; nt < 4; nt++)
                    mma_bf16(c[mt][nt], &a[mt][ks * 4], &b[nt][ks * 2]);
        __syncthreads();
    }

    // epilogue
#pragma unroll
    for (int mt = 0; mt < 4; mt++) {
#pragma unroll
        for (int nt = 0; nt < 4; nt++) {
            int n = n0 + wn * 32 + nt * 8 + 2 * tg;
            float bx = bias[n], by = bias[n + 1];
#pragma unroll
            for (int hh = 0; hh < 2; hh++) {
                int r = m0 + wm * 64 + mt * 16 + g + hh * 8;
                float vx = c[mt][nt][2 * hh] + bx;
                float vy = c[mt][nt][2 * hh + 1] + by;
                if (mode == 0) {
                    *(float2*)(outp + (size_t)r * EE + n) = make_float2(vx, vy);
                } else {
                    if (mode == 1) { vx *= 0.125f; vy *= 0.125f; }
                    uint32_t hp = pack_bf16x2(vx, vy);
                    uint32_t lp = pack_resid(vx, vy, hp);
                    int head = n >> 6, d = n & 63;
                    int bidx = r >> 11, srow = r & 2047;
                    size_t bh = (size_t)bidx * HH + head;
                    if (mode == 3) {
                        size_t i0 = (bh * DD + d) * SS + srow;
                        size_t i1 = (bh * DD + d + 1) * SS + srow;
                        g_vthi[i0] = __ushort_as_bfloat16((unsigned short)(hp & 0xffff));
                        g_vthi[i1] = __ushort_as_bfloat16((unsigned short)(hp >> 16));
                        g_vtlo[i0] = __ushort_as_bfloat16((unsigned short)(lp & 0xffff));
                        g_vtlo[i1] = __ushort_as_bfloat16((unsigned short)(lp >> 16));
                    } else {
                        size_t idx = (bh * SS + srow) * DD + d;
                        __nv_bfloat16* dh = (mode == 1) ? g_qhi : g_khi;
                        __nv_bfloat16* dl = (mode == 1) ? g_qlo : g_klo;
                        *(uint32_t*)(dh + idx) = hp;
                        *(uint32_t*)(dl + idx) = lp;
                    }
                }
            }
        }
    }
}

// ---------------------------------------------------------------------------
// tensor-core flash attention, bf16-split, ldmatrix fragments
// ---------------------------------------------------------------------------
#define QT 128
#define KT 64
#define PITCH 144
#define KV_TILE (KT * PITCH)
#define KV_STAGE (4 * KV_TILE)
#define OFF_QHI 8192
#define OFF_QLO (OFF_QHI + QT * PITCH)
#define OFF_ST  (OFF_QLO + QT * PITCH)
#define ATTN_SMEM (OFF_ST + 2 * KV_STAGE)

__global__ __launch_bounds__(256, 1)
void attn_tc() {
    extern __shared__ char sm[];
    float* bias_s = (float*)sm;
    uint32_t smb = smem_u32(sm);
    int tid = threadIdx.x, lane = tid & 31, w = tid >> 5;
    int g = lane >> 2, tg = lane & 3;
    int qt = blockIdx.x, h = blockIdx.y, b = blockIdx.z;
    int q0 = qt * QT;
    size_t bh = (size_t)b * HH + h;

    const __nv_bfloat16* Khi = g_khi + bh * SS * DD;
    const __nv_bfloat16* Klo = g_klo + bh * SS * DD;
    const __nv_bfloat16* Vhi = g_vthi + bh * DD * SS;
    const __nv_bfloat16* Vlo = g_vtlo + bh * DD * SS;
    const __nv_bfloat16* Qhi = g_qhi + (bh * SS + q0) * DD;
    const __nv_bfloat16* Qlo = g_qlo + (bh * SS + q0) * DD;

    const float4* br = (const float4*)(g_bias8 + h * SS);
    for (int i = tid; i < SS / 4; i += 256) ((float4*)bias_s)[i] = br[i];

#pragma unroll
    for (int i = 0; i < 4; i++) {
        int ch = tid + i * 256;
        int r = ch >> 3, cc = ch & 7;
        uint32_t off = r * PITCH + cc * 16;
        cp16(smb + OFF_QHI + off, Qhi + r * 64 + cc * 8);
        cp16(smb + OFF_QLO + off, Qlo + r * 64 + cc * 8);
    }
    auto load_kv = [&](int kt, int s) {
        uint32_t base = smb + OFF_ST + s * KV_STAGE;
        int k0 = kt * KT;
#pragma unroll
        for (int i = 0; i < 2; i++) {
            int ch = tid + i * 256;
            int r = ch >> 3, cc = ch & 7;
            uint32_t off = r * PITCH + cc * 16;
            cp16(base + off,               Khi + (size_t)(k0 + r) * 64 + cc * 8);
            cp16(base + KV_TILE + off,     Klo + (size_t)(k0 + r) * 64 + cc * 8);
            cp16(base + 2 * KV_TILE + off, Vhi + (size_t)r * SS + k0 + cc * 8);
            cp16(base + 3 * KV_TILE + off, Vlo + (size_t)r * SS + k0 + cc * 8);
        }
    };
    load_kv(0, 0);
    asm volatile("cp.async.commit_group;" ::: "memory");

    float m0 = -1e30f, m1 = -1e30f, l0 = 0.f, l1 = 0.f;
    float acc[8][4];
#pragma unroll
    for (int j = 0; j < 8; j++)
#pragma unroll
        for (int i = 0; i < 4; i++) acc[j][i] = 0.f;

    uint32_t qh[16], ql[16];
    int qrow0 = q0 + w * 16 + g;
    int qrow1 = qrow0 + 8;

    // ldmatrix lane components
    uint32_t a_lrow = ((uint32_t)((lane >> 3) & 1)) * 8 + (lane & 7);
    uint32_t a_lcol = ((uint32_t)(lane >> 4)) * 16;
    uint32_t kv_off = (lane & 7) * PITCH + ((uint32_t)(lane >> 3)) * 16;

    for (int kt = 0; kt < 32; kt++) {
        __syncthreads();
        if (kt + 1 < 32) load_kv(kt + 1, (kt + 1) & 1);
        asm volatile("cp.async.commit_group;" ::: "memory");
        asm volatile("cp.async.wait_group 1;" ::: "memory");
        __syncthreads();

        if (kt == 0) {
#pragma unroll
            for (int s = 0; s < 4; s++) {
                uint32_t base = smb + OFF_QHI + (w * 16 + a_lrow) * PITCH + s * 32 + a_lcol;
                ldsm_x4(&qh[4 * s], base);
                ldsm_x4(&ql[4 * s], base + (OFF_QLO - OFF_QHI));
            }
        }

        uint32_t stg = smb + OFF_ST + (kt & 1) * KV_STAGE;

        // ---- S = Q K^T (3-term split) ----
        float sc[8][4];
#pragma unroll
        for (int j = 0; j < 8; j++) {
#pragma unroll
            for (int i = 0; i < 4; i++) sc[j][i] = 0.f;
            uint32_t kbase = stg + j * (8 * PITCH) + kv_off;
            uint32_t kh[8], kl[8];
            ldsm_x4(&kh[0], kbase);
            ldsm_x4(&kh[4], kbase + 64);
            ldsm_x4(&kl[0], kbase + KV_TILE);
            ldsm_x4(&kl[4], kbase + KV_TILE + 64);
#pragma unroll
            for (int s = 0; s < 4; s++) {
                mma_bf16(sc[j], &qh[4 * s], &kh[2 * s]);
                mma_bf16(sc[j], &ql[4 * s], &kh[2 * s]);
                mma_bf16(sc[j], &qh[4 * s], &kl[2 * s]);
            }
        }

        // ---- bias add ----
        int colb = kt * KT + 2 * tg;
#pragma unroll
        for (int j = 0; j < 8; j++) {
            int col = colb + 8 * j;
            int d0 = qrow0 - col, d1 = qrow1 - col;
            sc[j][0] += bias_s[max(d0, 0)];
            sc[j][1] += bias_s[max(d0 - 1, 0)];
            sc[j][2] += bias_s[max(d1, 0)];
            sc[j][3] += bias_s[max(d1 - 1, 0)];
        }

        // ---- online softmax ----
        float mt0 = sc[0][0], mt1 = sc[0][2];
#pragma unroll
        for (int j = 0; j < 8; j++) {
            mt0 = fmaxf(mt0, fmaxf(sc[j][0], sc[j][1]));
            mt1 = fmaxf(mt1, fmaxf(sc[j][2], sc[j][3]));
        }
        mt0 = fmaxf(mt0, __shfl_xor_sync(0xffffffffu, mt0, 1));
        mt0 = fmaxf(mt0, __shfl_xor_sync(0xffffffffu, mt0, 2));
        mt1 = fmaxf(mt1, __shfl_xor_sync(0xffffffffu, mt1, 1));
        mt1 = fmaxf(mt1, __shfl_xor_sync(0xffffffffu, mt1, 2));
        float mn0 = fmaxf(m0, mt0), mn1 = fmaxf(m1, mt1);
        float cr0 = __expf(m0 - mn0), cr1 = __expf(m1 - mn1);
        float ps0 = 0.f, ps1 = 0.f;
#pragma unroll
        for (int j = 0; j < 8; j++) {
            sc[j][0] = __expf(sc[j][0] - mn0);
            sc[j][1] = __expf(sc[j][1] - mn0);
            sc[j][2] = __expf(sc[j][2] - mn1);
            sc[j][3] = __expf(sc[j][3] - mn1);
            ps0 += sc[j][0] + sc[j][1];
            ps1 += sc[j][2] + sc[j][3];
        }
        ps0 += __shfl_xor_sync(0xffffffffu, ps0, 1);
        ps0 += __shfl_xor_sync(0xffffffffu, ps0, 2);
        ps1 += __shfl_xor_sync(0xffffffffu, ps1, 1);
        ps1 += __shfl_xor_sync(0xffffffffu, ps1, 2);
        l0 = l0 * cr0 + ps0;  m0 = mn0;
        l1 = l1 * cr1 + ps1;  m1 = mn1;
#pragma unroll
        for (int j = 0; j < 8; j++) {
            acc[j][0] *= cr0; acc[j][1] *= cr0;
            acc[j][2] *= cr1; acc[j][3] *= cr1;
        }

        // ---- P -> bf16 hi/lo fragments ----
        uint32_t ph[8], ph2[8], pl[8], pl2[8];
#pragma unroll
        for (int j = 0; j < 8; j++) {
            ph[j]  = pack_bf16x2(sc[j][0], sc[j][1]);
            pl[j]  = pack_resid(sc[j][0], sc[j][1], ph[j]);
            ph2[j] = pack_bf16x2(sc[j][2], sc[j][3]);
            pl2[j] = pack_resid(sc[j][2], sc[j][3], ph2[j]);
        }

        // ---- O += P V (3-term split) ----
#pragma unroll
        for (int j = 0; j < 8; j++) {
            uint32_t vbase = stg + 2 * KV_TILE + j * (8 * PITCH) + kv_off;
            uint32_t vh[8], vl[8];
            ldsm_x4(&vh[0], vbase);
            ldsm_x4(&vh[4], vbase + 64);
            ldsm_x4(&vl[0], vbase + KV_TILE);
            ldsm_x4(&vl[4], vbase + KV_TILE + 64);
#pragma unroll
            for (int s = 0; s < 4; s++) {
                uint32_t pA[4] = { ph[2*s], ph2[2*s], ph[2*s+1], ph2[2*s+1] };
                uint32_t pL[4] = { pl[2*s], pl2[2*s], pl[2*s+1], pl2[2*s+1] };
                mma_bf16(acc[j], pA, &vh[2 * s]);
                mma_bf16(acc[j], pL, &vh[2 * s]);
                mma_bf16(acc[j], pA, &vl[2 * s]);
            }
        }
    }

    // ---- epilogue ----
    float inv0 = 1.f / l0, inv1 = 1.f / l1;
#pragma unroll
    for (int j = 0; j < 8; j++) {
        int e = h * 64 + 8 * j + 2 * tg;
        {
            float ox = acc[j][0] * inv0, oy = acc[j][1] * inv0;
            uint32_t hp = pack_bf16x2(ox, oy);
            uint32_t lp = pack_resid(ox, oy, hp);
            size_t base = ((size_t)b * SS + qrow0) * EE + e;
            *(uint32_t*)(g_chi + base) = hp;
            *(uint32_t*)(g_clo + base) = lp;
        }
        {
            float ox = acc[j][2] * inv1, oy = acc[j][3] * inv1;
            uint32_t hp = pack_bf16x2(ox, oy);
            uint32_t lp = pack_resid(ox, oy, hp);
            size_t base = ((size_t)b * SS + qrow1) * EE + e;
            *(uint32_t*)(g_chi + base) = hp;
            *(uint32_t*)(g_clo + base) = lp;
        }
    }
}

// ---------------------------------------------------------------------------
// Launcher
// ---------------------------------------------------------------------------
extern "C" void kernel_launch(void* const* d_in, const int* in_sizes, int n_in,
                              void* d_out, int out_size) {
    const float* hs  = (const float*)d_in[0];
    const float* Wq  = (const float*)d_in[1];
    const float* bq  = (const float*)d_in[2];
    const float* Wk  = (const float*)d_in[3];
    const float* bk  = (const float*)d_in[4];
    const float* Wv  = (const float*)d_in[5];
    const float* bv  = (const float*)d_in[6];
    const float* Wo  = (const float*)d_in[7];
    const float* bo  = (const float*)d_in[8];
    const float* rel = (const float*)d_in[9];
    float* out = (float*)d_out;

    cudaFuncSetAttribute(gemm_mma, cudaFuncAttributeMaxDynamicSharedMemorySize, GSMEM);
    cudaFuncSetAttribute(attn_tc, cudaFuncAttributeMaxDynamicSharedMemorySize, ATTN_SMEM);

    bias_kernel<<<(HH * SS + 255) / 256, 256>>>(rel);
    split_kernel<<<(MTOT * EE / 4 + 255) / 256, 256>>>(hs);
    dim3 wgrid(32, 32), wblk(32, 8);
    wt_split_kernel<<<wgrid, wblk>>>(Wq, 0);
    wt_split_kernel<<<wgrid, wblk>>>(Wk, 1);
    wt_split_kernel<<<wgrid, wblk>>>(Wv, 2);
    wt_split_kernel<<<wgrid, wblk>>>(Wo, 3);

    dim3 ggrid(EE / BN, MTOT / BM);
    gemm_mma<<<ggrid, 256, GSMEM>>>(bq, out, 1);
    gemm_mma<<<ggrid, 256, GSMEM>>>(bk, out, 2);
    gemm_mma<<<ggrid, 256, GSMEM>>>(bv, out, 3);

    dim3 agrid(SS / QT, HH, BB);
    attn_tc<<<agrid, 256, ATTN_SMEM>>>();

    gemm_mma<<<ggrid, 256, GSMEM>>>(bo, out, 0);
}

// round 6
// speedup vs baseline: 1.6859x; 1.6859x over previous
#include <cuda_runtime.h>
#include <cuda_fp16.h>
#include <stdint.h>
#include <math.h>

#define BB 2
#define SS 2048
#define EE 1024
#define HH 16
#define DD 64
#define MTOT (BB*SS)

// ---------------------------------------------------------------------------
// Scratch (device globals — no allocation allowed)
// ---------------------------------------------------------------------------
__device__ float g_bias8[HH*SS];
__device__ __half g_ahi[MTOT*EE], g_alo[MTOT*EE];      // hs 2-term split
__device__ __half g_wthi[4u*EE*EE];                    // W^T fp16 (hi only)
__device__ __half g_chi[MTOT*EE], g_clo[MTOT*EE];      // ctx 2-term split
__device__ __half g_qhi[BB*HH*SS*DD], g_qlo[BB*HH*SS*DD];  // [b][h][s][d] (unscaled)
__device__ __half g_khi[BB*HH*SS*DD];                      // [b][h][s][d]
__device__ __half g_vthi[BB*HH*SS*DD];                     // [b][h][d][s]

// ---------------------------------------------------------------------------
// helpers
// ---------------------------------------------------------------------------
__device__ __forceinline__ uint32_t smem_u32(const void* p) {
    uint32_t r;
    asm("{ .reg .u64 t; cvta.to.shared.u64 t, %1; cvt.u32.u64 %0, t; }"
        : "=r"(r) : "l"(p));
    return r;
}

__device__ __forceinline__ void cp16(uint32_t dst, const void* src) {
    asm volatile("cp.async.cg.shared.global [%0], [%1], 16;"
                 :: "r"(dst), "l"(__cvta_generic_to_global(src)) : "memory");
}

__device__ __forceinline__ void mma_f16(float* c, const uint32_t* a, const uint32_t* b) {
    asm volatile(
        "mma.sync.aligned.m16n8k16.row.col.f32.f16.f16.f32 "
        "{%0,%1,%2,%3}, {%4,%5,%6,%7}, {%8,%9}, {%0,%1,%2,%3};"
        : "+f"(c[0]), "+f"(c[1]), "+f"(c[2]), "+f"(c[3])
        : "r"(a[0]), "r"(a[1]), "r"(a[2]), "r"(a[3]), "r"(b[0]), "r"(b[1]));
}

__device__ __forceinline__ void ldsm_x4(uint32_t* r, uint32_t addr) {
    asm volatile("ldmatrix.sync.aligned.m8n8.x4.shared.b16 {%0,%1,%2,%3}, [%4];"
        : "=r"(r[0]), "=r"(r[1]), "=r"(r[2]), "=r"(r[3]) : "r"(addr));
}

// pack {lo=a, hi=b} as f16x2
__device__ __forceinline__ uint32_t pack_f16x2(float a, float b) {
    uint32_t d;
    asm("cvt.rn.f16x2.f32 %0, %1, %2;" : "=r"(d) : "f"(b), "f"(a));
    return d;
}
__device__ __forceinline__ uint32_t pack_resid_f16(float a, float b, uint32_t hi) {
    __half2 h = *reinterpret_cast<__half2*>(&hi);
    float2 f = __half22float2(h);
    return pack_f16x2(a - f.x, b - f.y);
}

// ---------------------------------------------------------------------------
// bias table
// ---------------------------------------------------------------------------
__global__ void bias_kernel(const float* __restrict__ rel_bias) {
    int idx = blockIdx.x * blockDim.x + threadIdx.x;
    if (idx >= HH * SS) return;
    int h = idx / SS;
    int d = idx % SS;
    int bucket;
    if (d < 16) {
        bucket = d;
    } else {
        float t = (logf((float)d * 0.0625f) / 1.3862943611198906f) * 16.0f;
        int lb = 16 + (int)t;
        bucket = lb < 31 ? lb : 31;
    }
    g_bias8[idx] = rel_bias[bucket * HH + h] * 8.0f;
}

// ---------------------------------------------------------------------------
// split fp32 -> fp16 hi/lo for hs
// ---------------------------------------------------------------------------
__global__ void split_kernel(const float* __restrict__ in) {
    int i = blockIdx.x * blockDim.x + threadIdx.x;
    if (i >= MTOT * EE / 4) return;
    float4 v = ((const float4*)in)[i];
    uint32_t h01 = pack_f16x2(v.x, v.y), h23 = pack_f16x2(v.z, v.w);
    uint32_t l01 = pack_resid_f16(v.x, v.y, h01), l23 = pack_resid_f16(v.z, v.w, h23);
    ((uint32_t*)g_ahi)[i * 2] = h01;  ((uint32_t*)g_ahi)[i * 2 + 1] = h23;
    ((uint32_t*)g_alo)[i * 2] = l01;  ((uint32_t*)g_alo)[i * 2 + 1] = l23;
}

// ---------------------------------------------------------------------------
// transpose weights -> fp16 [N][K], all 4 in one launch
// ---------------------------------------------------------------------------
__global__ void wt_hi_kernel(const float* __restrict__ W0, const float* __restrict__ W1,
                             const float* __restrict__ W2, const float* __restrict__ W3) {
    __shared__ float t[32][33];
    int widx = blockIdx.z;
    const float* W = (widx == 0) ? W0 : (widx == 1) ? W1 : (widx == 2) ? W2 : W3;
    int n0 = blockIdx.x * 32, k0 = blockIdx.y * 32;
    int tx = threadIdx.x, ty = threadIdx.y;
#pragma unroll
    for (int i = 0; i < 4; i++)
        t[ty + i * 8][tx] = W[(size_t)(k0 + ty + i * 8) * EE + n0 + tx];
    __syncthreads();
    __half* hi = g_wthi + (size_t)widx * EE * EE;
#pragma unroll
    for (int i = 0; i < 4; i++) {
        int n = n0 + ty + i * 8, k = k0 + tx;
        hi[(size_t)n * EE + k] = __float2half(t[tx][ty + i * 8]);
    }
}

// ---------------------------------------------------------------------------
// mma.sync fp16 2-term GEMM:  C = (Ahi + Alo) @ Whi + bias
//   per k-iter stage holds {Ahi, Alo, B} tiles of [128 x 32]
// ---------------------------------------------------------------------------
#define BM 128
#define BN 128
#define NSTAGE 4
#define RPAD 80
#define TILE_BYTES (128 * RPAD)
#define STAGE_BYTES (3 * TILE_BYTES)
#define GSMEM (NSTAGE * STAGE_BYTES)
#define NITER 32

__global__ __launch_bounds__(256, 1)
void gemm_mma(const float* __restrict__ bias, float* __restrict__ outp, int mode) {
    extern __shared__ char sm[];
    int tid = threadIdx.x;
    int lane = tid & 31, wid = tid >> 5;
    int wm = wid & 1, wn = wid >> 1;           // 2 m-warps x 4 n-warps
    int g = lane >> 2, tg = lane & 3;
    int m0 = blockIdx.y * BM, n0 = blockIdx.x * BN;

    const __half* Ahi = (mode == 0) ? g_chi : g_ahi;
    const __half* Alo = (mode == 0) ? g_clo : g_alo;
    int widx = (mode == 0) ? 3 : (mode - 1);
    const __half* Bhi = g_wthi + (size_t)widx * EE * EE;

    float c[4][4][4];
#pragma unroll
    for (int mt = 0; mt < 4; mt++)
#pragma unroll
        for (int nt = 0; nt < 4; nt++)
#pragma unroll
            for (int i = 0; i < 4; i++) c[mt][nt][i] = 0.f;

    uint32_t smbase = smem_u32(sm);
    uint32_t a_lrow = ((uint32_t)((lane >> 3) & 1)) * 8 + (lane & 7);
    uint32_t a_lcol = ((uint32_t)(lane >> 4)) * 16;
    uint32_t b_lrow = lane & 7;
    uint32_t b_lcol = ((uint32_t)(lane >> 3)) * 16;

    auto load_stage = [&](int git, int s) {
        int kb = git * 32;
        uint32_t st = smbase + s * STAGE_BYTES;
#pragma unroll
        for (int i = 0; i < 2; i++) {
            int ch = tid + i * 256;
            int m = ch >> 2, k16 = ch & 3;
            uint32_t off = m * RPAD + k16 * 16;
            size_t ga = (size_t)(m0 + m) * EE + kb + k16 * 8;
            cp16(st + off,                  Ahi + ga);
            cp16(st + TILE_BYTES + off,     Alo + ga);
            cp16(st + 2 * TILE_BYTES + off, Bhi + (size_t)(n0 + m) * EE + kb + k16 * 8);
        }
    };

#pragma unroll
    for (int p = 0; p < NSTAGE - 1; p++) {
        load_stage(p, p);
        asm volatile("cp.async.commit_group;" ::: "memory");
    }

    for (int git = 0; git < NITER; git++) {
        asm volatile("cp.async.wait_group %0;" :: "n"(NSTAGE - 2) : "memory");
        __syncthreads();

        int nx = git + NSTAGE - 1;
        if (nx < NITER) load_stage(nx, nx & (NSTAGE - 1));
        asm volatile("cp.async.commit_group;" ::: "memory");

        uint32_t st = smbase + (git & (NSTAGE - 1)) * STAGE_BYTES;
        uint32_t Bs = st + 2 * TILE_BYTES;

        uint32_t b[4][4];
#pragma unroll
        for (int nt = 0; nt < 4; nt++)
            ldsm_x4(b[nt], Bs + (wn * 32 + nt * 8 + b_lrow) * RPAD + b_lcol);

#pragma unroll
        for (int seg = 0; seg < 2; seg++) {
            uint32_t As = st + seg * TILE_BYTES;
            uint32_t a[4][8];
#pragma unroll
            for (int mt = 0; mt < 4; mt++)
#pragma unroll
                for (int ks = 0; ks < 2; ks++)
                    ldsm_x4(&a[mt][ks * 4],
                            As + (wm * 64 + mt * 16 + a_lrow) * RPAD + ks * 32 + a_lcol);
#pragma unroll
            for (int ks = 0; ks < 2; ks++)
#pragma unroll
                for (int mt = 0; mt < 4; mt++)
#pragma unroll
                    for (int nt = 0; nt < 4; nt++)
                        mma_f16(c[mt][nt], &a[mt][ks * 4], &b[nt][ks * 2]);
        }
        __syncthreads();
    }

    // epilogue
#pragma unroll
    for (int mt = 0; mt < 4; mt++) {
#pragma unroll
        for (int nt = 0; nt < 4; nt++) {
            int n = n0 + wn * 32 + nt * 8 + 2 * tg;
            float bx = bias[n], by = bias[n + 1];
#pragma unroll
            for (int hh = 0; hh < 2; hh++) {
                int r = m0 + wm * 64 + mt * 16 + g + hh * 8;
                float vx = c[mt][nt][2 * hh] + bx;
                float vy = c[mt][nt][2 * hh + 1] + by;
                if (mode == 0) {
                    *(float2*)(outp + (size_t)r * EE + n) = make_float2(vx, vy);
                } else {
                    uint32_t hp = pack_f16x2(vx, vy);
                    int head = n >> 6, d = n & 63;
                    int bidx = r >> 11, srow = r & 2047;
                    size_t bh = (size_t)bidx * HH + head;
                    if (mode == 3) {
                        size_t i0 = (bh * DD + d) * SS + srow;
                        size_t i1 = (bh * DD + d + 1) * SS + srow;
                        g_vthi[i0] = __ushort_as_half((unsigned short)(hp & 0xffff));
                        g_vthi[i1] = __ushort_as_half((unsigned short)(hp >> 16));
                    } else if (mode == 2) {
                        *(uint32_t*)(g_khi + (bh * SS + srow) * DD + d) = hp;
                    } else {
                        uint32_t lp = pack_resid_f16(vx, vy, hp);
                        size_t idx = (bh * SS + srow) * DD + d;
                        *(uint32_t*)(g_qhi + idx) = hp;
                        *(uint32_t*)(g_qlo + idx) = lp;
                    }
                }
            }
        }
    }
}

// ---------------------------------------------------------------------------
// tensor-core flash attention, fp16 2-term
//   S = (Qhi+Qlo)·Khi, scaled 0.125 in bias FMA;  O = (Phi+Plo)·Vhi
// ---------------------------------------------------------------------------
#define QT 128
#define KT 64
#define PITCH 144
#define KV_TILE (KT * PITCH)
#define KV_STAGE (2 * KV_TILE)
#define OFF_QHI 8192
#define OFF_QLO (OFF_QHI + QT * PITCH)
#define OFF_ST  (OFF_QLO + QT * PITCH)
#define ATTN_SMEM (OFF_ST + 2 * KV_STAGE)

__global__ __launch_bounds__(256, 1)
void attn_tc() {
    extern __shared__ char sm[];
    float* bias_s = (float*)sm;
    uint32_t smb = smem_u32(sm);
    int tid = threadIdx.x, lane = tid & 31, w = tid >> 5;
    int g = lane >> 2, tg = lane & 3;
    int qt = blockIdx.x, h = blockIdx.y, b = blockIdx.z;
    int q0 = qt * QT;
    size_t bh = (size_t)b * HH + h;

    const __half* Khi = g_khi + bh * SS * DD;
    const __half* Vhi = g_vthi + bh * DD * SS;
    const __half* Qhi = g_qhi + (bh * SS + q0) * DD;
    const __half* Qlo = g_qlo + (bh * SS + q0) * DD;

    const float4* br = (const float4*)(g_bias8 + h * SS);
    for (int i = tid; i < SS / 4; i += 256) ((float4*)bias_s)[i] = br[i];

#pragma unroll
    for (int i = 0; i < 4; i++) {
        int ch = tid + i * 256;
        int r = ch >> 3, cc = ch & 7;
        uint32_t off = r * PITCH + cc * 16;
        cp16(smb + OFF_QHI + off, Qhi + r * 64 + cc * 8);
        cp16(smb + OFF_QLO + off, Qlo + r * 64 + cc * 8);
    }
    auto load_kv = [&](int kt, int s) {
        uint32_t base = smb + OFF_ST + s * KV_STAGE;
        int k0 = kt * KT;
#pragma unroll
        for (int i = 0; i < 2; i++) {
            int ch = tid + i * 256;
            int r = ch >> 3, cc = ch & 7;
            uint32_t off = r * PITCH + cc * 16;
            cp16(base + off,           Khi + (size_t)(k0 + r) * 64 + cc * 8);
            cp16(base + KV_TILE + off, Vhi + (size_t)r * SS + k0 + cc * 8);
        }
    };
    load_kv(0, 0);
    asm volatile("cp.async.commit_group;" ::: "memory");

    float m0 = -1e30f, m1 = -1e30f, l0 = 0.f, l1 = 0.f;
    float acc[8][4];
#pragma unroll
    for (int j = 0; j < 8; j++)
#pragma unroll
        for (int i = 0; i < 4; i++) acc[j][i] = 0.f;

    uint32_t qh[16], ql[16];
    int qrow0 = q0 + w * 16 + g;
    int qrow1 = qrow0 + 8;

    uint32_t a_lrow = ((uint32_t)((lane >> 3) & 1)) * 8 + (lane & 7);
    uint32_t a_lcol = ((uint32_t)(lane >> 4)) * 16;
    uint32_t kv_off = (lane & 7) * PITCH + ((uint32_t)(lane >> 3)) * 16;

    for (int kt = 0; kt < 32; kt++) {
        __syncthreads();
        if (kt + 1 < 32) load_kv(kt + 1, (kt + 1) & 1);
        asm volatile("cp.async.commit_group;" ::: "memory");
        asm volatile("cp.async.wait_group 1;" ::: "memory");
        __syncthreads();

        if (kt == 0) {
#pragma unroll
            for (int s = 0; s < 4; s++) {
                uint32_t base = smb + OFF_QHI + (w * 16 + a_lrow) * PITCH + s * 32 + a_lcol;
                ldsm_x4(&qh[4 * s], base);
                ldsm_x4(&ql[4 * s], base + (OFF_QLO - OFF_QHI));
            }
        }

        uint32_t stg = smb + OFF_ST + (kt & 1) * KV_STAGE;

        // ---- S = Q K^T (2-term) ----
        float sc[8][4];
#pragma unroll
        for (int j = 0; j < 8; j++) {
#pragma unroll
            for (int i = 0; i < 4; i++) sc[j][i] = 0.f;
            uint32_t kbase = stg + j * (8 * PITCH) + kv_off;
            uint32_t kh[8];
            ldsm_x4(&kh[0], kbase);
            ldsm_x4(&kh[4], kbase + 64);
#pragma unroll
            for (int s = 0; s < 4; s++) {
                mma_f16(sc[j], &qh[4 * s], &kh[2 * s]);
                mma_f16(sc[j], &ql[4 * s], &kh[2 * s]);
            }
        }

        // ---- scale + bias (fma) ----
        int colb = kt * KT + 2 * tg;
#pragma unroll
        for (int j = 0; j < 8; j++) {
            int col = colb + 8 * j;
            int d0 = qrow0 - col, d1 = qrow1 - col;
            sc[j][0] = sc[j][0] * 0.125f + bias_s[max(d0, 0)];
            sc[j][1] = sc[j][1] * 0.125f + bias_s[max(d0 - 1, 0)];
            sc[j][2] = sc[j][2] * 0.125f + bias_s[max(d1, 0)];
            sc[j][3] = sc[j][3] * 0.125f + bias_s[max(d1 - 1, 0)];
        }

        // ---- online softmax ----
        float mt0 = sc[0][0], mt1 = sc[0][2];
#pragma unroll
        for (int j = 0; j < 8; j++) {
            mt0 = fmaxf(mt0, fmaxf(sc[j][0], sc[j][1]));
            mt1 = fmaxf(mt1, fmaxf(sc[j][2], sc[j][3]));
        }
        mt0 = fmaxf(mt0, __shfl_xor_sync(0xffffffffu, mt0, 1));
        mt0 = fmaxf(mt0, __shfl_xor_sync(0xffffffffu, mt0, 2));
        mt1 = fmaxf(mt1, __shfl_xor_sync(0xffffffffu, mt1, 1));
        mt1 = fmaxf(mt1, __shfl_xor_sync(0xffffffffu, mt1, 2));
        float mn0 = fmaxf(m0, mt0), mn1 = fmaxf(m1, mt1);
        float cr0 = __expf(m0 - mn0), cr1 = __expf(m1 - mn1);
        float ps0 = 0.f, ps1 = 0.f;
#pragma unroll
        for (int j = 0; j < 8; j++) {
            sc[j][0] = __expf(sc[j][0] - mn0);
            sc[j][1] = __expf(sc[j][1] - mn0);
            sc[j][2] = __expf(sc[j][2] - mn1);
            sc[j][3] = __expf(sc[j][3] - mn1);
            ps0 += sc[j][0] + sc[j][1];
            ps1 += sc[j][2] + sc[j][3];
        }
        ps0 += __shfl_xor_sync(0xffffffffu, ps0, 1);
        ps0 += __shfl_xor_sync(0xffffffffu, ps0, 2);
        ps1 += __shfl_xor_sync(0xffffffffu, ps1, 1);
        ps1 += __shfl_xor_sync(0xffffffffu, ps1, 2);
        l0 = l0 * cr0 + ps0;  m0 = mn0;
        l1 = l1 * cr1 + ps1;  m1 = mn1;
#pragma unroll
        for (int j = 0; j < 8; j++) {
            acc[j][0] *= cr0; acc[j][1] *= cr0;
            acc[j][2] *= cr1; acc[j][3] *= cr1;
        }

        // ---- P -> fp16 hi/lo fragments ----
        uint32_t ph[8], ph2[8], pl[8], pl2[8];
#pragma unroll
        for (int j = 0; j < 8; j++) {
            ph[j]  = pack_f16x2(sc[j][0], sc[j][1]);
            pl[j]  = pack_resid_f16(sc[j][0], sc[j][1], ph[j]);
            ph2[j] = pack_f16x2(sc[j][2], sc[j][3]);
            pl2[j] = pack_resid_f16(sc[j][2], sc[j][3], ph2[j]);
        }

        // ---- O += P V (2-term) ----
#pragma unroll
        for (int j = 0; j < 8; j++) {
            uint32_t vbase = stg + KV_TILE + j * (8 * PITCH) + kv_off;
            uint32_t vh[8];
            ldsm_x4(&vh[0], vbase);
            ldsm_x4(&vh[4], vbase + 64);
#pragma unroll
            for (int s = 0; s < 4; s++) {
                uint32_t pA[4] = { ph[2*s], ph2[2*s], ph[2*s+1], ph2[2*s+1] };
                uint32_t pL[4] = { pl[2*s], pl2[2*s], pl[2*s+1], pl2[2*s+1] };
                mma_f16(acc[j], pA, &vh[2 * s]);
                mma_f16(acc[j], pL, &vh[2 * s]);
            }
        }
    }

    // ---- epilogue: normalize, write ctx split ----
    float inv0 = 1.f / l0, inv1 = 1.f / l1;
#pragma unroll
    for (int j = 0; j < 8; j++) {
        int e = h * 64 + 8 * j + 2 * tg;
        {
            float ox = acc[j][0] * inv0, oy = acc[j][1] * inv0;
            uint32_t hp = pack_f16x2(ox, oy);
            uint32_t lp = pack_resid_f16(ox, oy, hp);
            size_t base = ((size_t)b * SS + qrow0) * EE + e;
            *(uint32_t*)(g_chi + base) = hp;
            *(uint32_t*)(g_clo + base) = lp;
        }
        {
            float ox = acc[j][2] * inv1, oy = acc[j][3] * inv1;
            uint32_t hp = pack_f16x2(ox, oy);
            uint32_t lp = pack_resid_f16(ox, oy, hp);
            size_t base = ((size_t)b * SS + qrow1) * EE + e;
            *(uint32_t*)(g_chi + base) = hp;
            *(uint32_t*)(g_clo + base) = lp;
        }
    }
}

// ---------------------------------------------------------------------------
// Launcher
// ---------------------------------------------------------------------------
extern "C" void kernel_launch(void* const* d_in, const int* in_sizes, int n_in,
                              void* d_out, int out_size) {
    const float* hs  = (const float*)d_in[0];
    const float* Wq  = (const float*)d_in[1];
    const float* bq  = (const float*)d_in[2];
    const float* Wk  = (const float*)d_in[3];
    const float* bk  = (const float*)d_in[4];
    const float* Wv  = (const float*)d_in[5];
    const float* bv  = (const float*)d_in[6];
    const float* Wo  = (const float*)d_in[7];
    const float* bo  = (const float*)d_in[8];
    const float* rel = (const float*)d_in[9];
    float* out = (float*)d_out;

    cudaFuncSetAttribute(gemm_mma, cudaFuncAttributeMaxDynamicSharedMemorySize, GSMEM);
    cudaFuncSetAttribute(attn_tc, cudaFuncAttributeMaxDynamicSharedMemorySize, ATTN_SMEM);

    bias_kernel<<<(HH * SS + 255) / 256, 256>>>(rel);
    split_kernel<<<(MTOT * EE / 4 + 255) / 256, 256>>>(hs);
    dim3 wgrid(32, 32, 4), wblk(32, 8);
    wt_hi_kernel<<<wgrid, wblk>>>(Wq, Wk, Wv, Wo);

    dim3 ggrid(EE / BN, MTOT / BM);   // (8, 32)
    gemm_mma<<<ggrid, 256, GSMEM>>>(bq, out, 1);
    gemm_mma<<<ggrid, 256, GSMEM>>>(bk, out, 2);
    gemm_mma<<<ggrid, 256, GSMEM>>>(bv, out, 3);

    dim3 agrid(SS / QT, HH, BB);      // (16, 16, 2)
    attn_tc<<<agrid, 256, ATTN_SMEM>>>();

    gemm_mma<<<ggrid, 256, GSMEM>>>(bo, out, 0);
}

// round 7
// speedup vs baseline: 1.7255x; 1.0235x over previous
#include <cuda_runtime.h>
#include <cuda_fp16.h>
#include <stdint.h>
#include <math.h>

#define BB 2
#define SS 2048
#define EE 1024
#define HH 16
#define DD 64
#define MTOT (BB*SS)

// ---------------------------------------------------------------------------
// Scratch (device globals — no allocation allowed)
// ---------------------------------------------------------------------------
__device__ float g_bias8[HH*SS];
__device__ __half g_ahi[MTOT*EE], g_alo[MTOT*EE];      // hs 2-term split
__device__ __half g_wthi[4u*EE*EE];                    // W^T fp16 (q,k,v,o)
__device__ __half g_chi[MTOT*EE], g_clo[MTOT*EE];      // ctx 2-term split
__device__ __half g_qhi[BB*HH*SS*DD], g_qlo[BB*HH*SS*DD];  // [b][h][s][d] (unscaled)
__device__ __half g_khi[BB*HH*SS*DD];                      // [b][h][s][d]
__device__ __half g_vthi[BB*HH*SS*DD];                     // [b][h][d][s]

// ---------------------------------------------------------------------------
// helpers
// ---------------------------------------------------------------------------
__device__ __forceinline__ uint32_t smem_u32(const void* p) {
    uint32_t r;
    asm("{ .reg .u64 t; cvta.to.shared.u64 t, %1; cvt.u32.u64 %0, t; }"
        : "=r"(r) : "l"(p));
    return r;
}

__device__ __forceinline__ void cp16(uint32_t dst, const void* src) {
    asm volatile("cp.async.cg.shared.global [%0], [%1], 16;"
                 :: "r"(dst), "l"(__cvta_generic_to_global(src)) : "memory");
}

__device__ __forceinline__ void mma_f16(float* c, const uint32_t* a, const uint32_t* b) {
    asm volatile(
        "mma.sync.aligned.m16n8k16.row.col.f32.f16.f16.f32 "
        "{%0,%1,%2,%3}, {%4,%5,%6,%7}, {%8,%9}, {%0,%1,%2,%3};"
        : "+f"(c[0]), "+f"(c[1]), "+f"(c[2]), "+f"(c[3])
        : "r"(a[0]), "r"(a[1]), "r"(a[2]), "r"(a[3]), "r"(b[0]), "r"(b[1]));
}

__device__ __forceinline__ void ldsm_x4(uint32_t* r, uint32_t addr) {
    asm volatile("ldmatrix.sync.aligned.m8n8.x4.shared.b16 {%0,%1,%2,%3}, [%4];"
        : "=r"(r[0]), "=r"(r[1]), "=r"(r[2]), "=r"(r[3]) : "r"(addr));
}

__device__ __forceinline__ uint32_t pack_f16x2(float a, float b) {
    uint32_t d;
    asm("cvt.rn.f16x2.f32 %0, %1, %2;" : "=r"(d) : "f"(b), "f"(a));
    return d;
}
__device__ __forceinline__ uint32_t pack_resid_f16(float a, float b, uint32_t hi) {
    __half2 h = *reinterpret_cast<__half2*>(&hi);
    float2 f = __half22float2(h);
    return pack_f16x2(a - f.x, b - f.y);
}

// ---------------------------------------------------------------------------
// bias table
// ---------------------------------------------------------------------------
__global__ void bias_kernel(const float* __restrict__ rel_bias) {
    int idx = blockIdx.x * blockDim.x + threadIdx.x;
    if (idx >= HH * SS) return;
    int h = idx / SS;
    int d = idx % SS;
    int bucket;
    if (d < 16) {
        bucket = d;
    } else {
        float t = (logf((float)d * 0.0625f) / 1.3862943611198906f) * 16.0f;
        int lb = 16 + (int)t;
        bucket = lb < 31 ? lb : 31;
    }
    g_bias8[idx] = rel_bias[bucket * HH + h] * 8.0f;
}

// ---------------------------------------------------------------------------
// split fp32 -> fp16 hi/lo for hs
// ---------------------------------------------------------------------------
__global__ void split_kernel(const float* __restrict__ in) {
    int i = blockIdx.x * blockDim.x + threadIdx.x;
    if (i >= MTOT * EE / 4) return;
    float4 v = ((const float4*)in)[i];
    uint32_t h01 = pack_f16x2(v.x, v.y), h23 = pack_f16x2(v.z, v.w);
    uint32_t l01 = pack_resid_f16(v.x, v.y, h01), l23 = pack_resid_f16(v.z, v.w, h23);
    ((uint32_t*)g_ahi)[i * 2] = h01;  ((uint32_t*)g_ahi)[i * 2 + 1] = h23;
    ((uint32_t*)g_alo)[i * 2] = l01;  ((uint32_t*)g_alo)[i * 2 + 1] = l23;
}

// ---------------------------------------------------------------------------
// transpose weights -> fp16 [N][K]
// ---------------------------------------------------------------------------
__global__ void wt_hi_kernel(const float* __restrict__ W0, const float* __restrict__ W1,
                             const float* __restrict__ W2, const float* __restrict__ W3) {
    __shared__ float t[32][33];
    int widx = blockIdx.z;
    const float* W = (widx == 0) ? W0 : (widx == 1) ? W1 : (widx == 2) ? W2 : W3;
    int n0 = blockIdx.x * 32, k0 = blockIdx.y * 32;
    int tx = threadIdx.x, ty = threadIdx.y;
#pragma unroll
    for (int i = 0; i < 4; i++)
        t[ty + i * 8][tx] = W[(size_t)(k0 + ty + i * 8) * EE + n0 + tx];
    __syncthreads();
    __half* hi = g_wthi + (size_t)widx * EE * EE;
#pragma unroll
    for (int i = 0; i < 4; i++) {
        int n = n0 + ty + i * 8, k = k0 + tx;
        hi[(size_t)n * EE + k] = __float2half(t[tx][ty + i * 8]);
    }
}

// ---------------------------------------------------------------------------
// mma.sync fp16 2-term GEMM, 512 threads / 16 warps (4m x 4n), warp tile 32x32
//   mode 1: fused QKV  (grid.x = 24: widx = bx>>3)
//   mode 0: O-proj     (grid.x = 8)
// ---------------------------------------------------------------------------
#define BM 128
#define BN 128
#define NSTAGE 4
#define RPAD 80
#define TILE_BYTES (128 * RPAD)
#define STAGE_BYTES (3 * TILE_BYTES)
#define GSMEM (NSTAGE * STAGE_BYTES)
#define NITER 32

__global__ __launch_bounds__(512, 1)
void gemm_mma(const float* __restrict__ b0, const float* __restrict__ b1,
              const float* __restrict__ b2, float* __restrict__ outp, int mode) {
    extern __shared__ char sm[];
    int tid = threadIdx.x;
    int lane = tid & 31, wid = tid >> 5;
    int wm = wid & 3, wn = wid >> 2;           // 4 m-warps x 4 n-warps
    int g = lane >> 2, tg = lane & 3;
    int m0 = blockIdx.y * BM;

    int widx, n0;
    if (mode == 0) { widx = 3; n0 = blockIdx.x * BN; }
    else { widx = blockIdx.x >> 3; n0 = (blockIdx.x & 7) * BN; }

    const float* bias = (mode == 0) ? b0 : (widx == 0) ? b0 : (widx == 1) ? b1 : b2;
    const __half* Ahi = (mode == 0) ? g_chi : g_ahi;
    const __half* Alo = (mode == 0) ? g_clo : g_alo;
    const __half* Bhi = g_wthi + (size_t)widx * EE * EE;

    float c[2][4][4];
#pragma unroll
    for (int mt = 0; mt < 2; mt++)
#pragma unroll
        for (int nt = 0; nt < 4; nt++)
#pragma unroll
            for (int i = 0; i < 4; i++) c[mt][nt][i] = 0.f;

    uint32_t smbase = smem_u32(sm);
    uint32_t a_lrow = ((uint32_t)((lane >> 3) & 1)) * 8 + (lane & 7);
    uint32_t a_lcol = ((uint32_t)(lane >> 4)) * 16;
    uint32_t b_lrow = lane & 7;
    uint32_t b_lcol = ((uint32_t)(lane >> 3)) * 16;

    // per stage: each thread loads 1 chunk of each of {Ahi, Alo, B}
    int lm = tid >> 2, lk = tid & 3;
    auto load_stage = [&](int git, int s) {
        int kb = git * 32;
        uint32_t st = smbase + s * STAGE_BYTES;
        uint32_t off = lm * RPAD + lk * 16;
        size_t ga = (size_t)(m0 + lm) * EE + kb + lk * 8;
        cp16(st + off,                  Ahi + ga);
        cp16(st + TILE_BYTES + off,     Alo + ga);
        cp16(st + 2 * TILE_BYTES + off, Bhi + (size_t)(n0 + lm) * EE + kb + lk * 8);
    };

#pragma unroll
    for (int p = 0; p < NSTAGE - 1; p++) {
        load_stage(p, p);
        asm volatile("cp.async.commit_group;" ::: "memory");
    }

    for (int git = 0; git < NITER; git++) {
        asm volatile("cp.async.wait_group %0;" :: "n"(NSTAGE - 2) : "memory");
        __syncthreads();

        int nx = git + NSTAGE - 1;
        if (nx < NITER) load_stage(nx, nx & (NSTAGE - 1));
        asm volatile("cp.async.commit_group;" ::: "memory");

        uint32_t st = smbase + (git & (NSTAGE - 1)) * STAGE_BYTES;
        uint32_t Bs = st + 2 * TILE_BYTES;

        uint32_t b[4][4];
#pragma unroll
        for (int nt = 0; nt < 4; nt++)
            ldsm_x4(b[nt], Bs + (wn * 32 + nt * 8 + b_lrow) * RPAD + b_lcol);

#pragma unroll
        for (int seg = 0; seg < 2; seg++) {
            uint32_t As = st + seg * TILE_BYTES;
            uint32_t a[2][8];
#pragma unroll
            for (int mt = 0; mt < 2; mt++)
#pragma unroll
                for (int ks = 0; ks < 2; ks++)
                    ldsm_x4(&a[mt][ks * 4],
                            As + (wm * 32 + mt * 16 + a_lrow) * RPAD + ks * 32 + a_lcol);
#pragma unroll
            for (int ks = 0; ks < 2; ks++)
#pragma unroll
                for (int mt = 0; mt < 2; mt++)
#pragma unroll
                    for (int nt = 0; nt < 4; nt++)
                        mma_f16(c[mt][nt], &a[mt][ks * 4], &b[nt][ks * 2]);
        }
    }

    // epilogue
#pragma unroll
    for (int mt = 0; mt < 2; mt++) {
#pragma unroll
        for (int nt = 0; nt < 4; nt++) {
            int n = n0 + wn * 32 + nt * 8 + 2 * tg;
            float bx = bias[n], by = bias[n + 1];
#pragma unroll
            for (int hh = 0; hh < 2; hh++) {
                int r = m0 + wm * 32 + mt * 16 + g + hh * 8;
                float vx = c[mt][nt][2 * hh] + bx;
                float vy = c[mt][nt][2 * hh + 1] + by;
                if (mode == 0) {
                    *(float2*)(outp + (size_t)r * EE + n) = make_float2(vx, vy);
                } else {
                    uint32_t hp = pack_f16x2(vx, vy);
                    int head = n >> 6, d = n & 63;
                    int bidx = r >> 11, srow = r & 2047;
                    size_t bh = (size_t)bidx * HH + head;
                    if (widx == 2) {
                        size_t i0 = (bh * DD + d) * SS + srow;
                        size_t i1 = (bh * DD + d + 1) * SS + srow;
                        g_vthi[i0] = __ushort_as_half((unsigned short)(hp & 0xffff));
                        g_vthi[i1] = __ushort_as_half((unsigned short)(hp >> 16));
                    } else if (widx == 1) {
                        *(uint32_t*)(g_khi + (bh * SS + srow) * DD + d) = hp;
                    } else {
                        uint32_t lp = pack_resid_f16(vx, vy, hp);
                        size_t idx = (bh * SS + srow) * DD + d;
                        *(uint32_t*)(g_qhi + idx) = hp;
                        *(uint32_t*)(g_qlo + idx) = lp;
                    }
                }
            }
        }
    }
}

// ---------------------------------------------------------------------------
// tensor-core flash attention, fp16 2-term, 3-stage KV ring, 1 sync/iter
// ---------------------------------------------------------------------------
#define QT 128
#define KT 64
#define PITCH 144
#define KV_TILE (KT * PITCH)
#define KV_STAGE (2 * KV_TILE)
#define OFF_QHI 8192
#define OFF_QLO (OFF_QHI + QT * PITCH)
#define OFF_ST  (OFF_QLO + QT * PITCH)
#define ATTN_SMEM (OFF_ST + 3 * KV_STAGE)

__global__ __launch_bounds__(256, 1)
void attn_tc() {
    extern __shared__ char sm[];
    float* bias_s = (float*)sm;
    uint32_t smb = smem_u32(sm);
    int tid = threadIdx.x, lane = tid & 31, w = tid >> 5;
    int g = lane >> 2, tg = lane & 3;
    int qt = blockIdx.x, h = blockIdx.y, b = blockIdx.z;
    int q0 = qt * QT;
    size_t bh = (size_t)b * HH + h;

    const __half* Khi = g_khi + bh * SS * DD;
    const __half* Vhi = g_vthi + bh * DD * SS;
    const __half* Qhi = g_qhi + (bh * SS + q0) * DD;
    const __half* Qlo = g_qlo + (bh * SS + q0) * DD;

    const float4* br = (const float4*)(g_bias8 + h * SS);
    for (int i = tid; i < SS / 4; i += 256) ((float4*)bias_s)[i] = br[i];

    auto load_kv = [&](int kt, int s) {
        uint32_t base = smb + OFF_ST + s * KV_STAGE;
        int k0 = kt * KT;
#pragma unroll
        for (int i = 0; i < 2; i++) {
            int ch = tid + i * 256;
            int r = ch >> 3, cc = ch & 7;
            uint32_t off = r * PITCH + cc * 16;
            cp16(base + off,           Khi + (size_t)(k0 + r) * 64 + cc * 8);
            cp16(base + KV_TILE + off, Vhi + (size_t)r * SS + k0 + cc * 8);
        }
    };

    // prologue: group0 = Q + KV0, group1 = KV1
#pragma unroll
    for (int i = 0; i < 4; i++) {
        int ch = tid + i * 256;
        int r = ch >> 3, cc = ch & 7;
        uint32_t off = r * PITCH + cc * 16;
        cp16(smb + OFF_QHI + off, Qhi + r * 64 + cc * 8);
        cp16(smb + OFF_QLO + off, Qlo + r * 64 + cc * 8);
    }
    load_kv(0, 0);
    asm volatile("cp.async.commit_group;" ::: "memory");
    load_kv(1, 1);
    asm volatile("cp.async.commit_group;" ::: "memory");

    float m0 = -1e30f, m1 = -1e30f, l0 = 0.f, l1 = 0.f;
    float acc[8][4];
#pragma unroll
    for (int j = 0; j < 8; j++)
#pragma unroll
        for (int i = 0; i < 4; i++) acc[j][i] = 0.f;

    uint32_t qh[16], ql[16];
    int qrow0 = q0 + w * 16 + g;
    int qrow1 = qrow0 + 8;

    uint32_t a_lrow = ((uint32_t)((lane >> 3) & 1)) * 8 + (lane & 7);
    uint32_t a_lcol = ((uint32_t)(lane >> 4)) * 16;
    uint32_t kv_off = (lane & 7) * PITCH + ((uint32_t)(lane >> 3)) * 16;

    for (int kt = 0; kt < 32; kt++) {
        asm volatile("cp.async.wait_group 1;" ::: "memory");
        __syncthreads();

        if (kt + 2 < 32) load_kv(kt + 2, (kt + 2) % 3);
        asm volatile("cp.async.commit_group;" ::: "memory");

        if (kt == 0) {
#pragma unroll
            for (int s = 0; s < 4; s++) {
                uint32_t base = smb + OFF_QHI + (w * 16 + a_lrow) * PITCH + s * 32 + a_lcol;
                ldsm_x4(&qh[4 * s], base);
                ldsm_x4(&ql[4 * s], base + (OFF_QLO - OFF_QHI));
            }
        }

        uint32_t stg = smb + OFF_ST + (kt % 3) * KV_STAGE;

        // ---- S = Q K^T (2-term) ----
        float sc[8][4];
#pragma unroll
        for (int j = 0; j < 8; j++) {
#pragma unroll
            for (int i = 0; i < 4; i++) sc[j][i] = 0.f;
            uint32_t kbase = stg + j * (8 * PITCH) + kv_off;
            uint32_t kh[8];
            ldsm_x4(&kh[0], kbase);
            ldsm_x4(&kh[4], kbase + 64);
#pragma unroll
            for (int s = 0; s < 4; s++) {
                mma_f16(sc[j], &qh[4 * s], &kh[2 * s]);
                mma_f16(sc[j], &ql[4 * s], &kh[2 * s]);
            }
        }

        // ---- scale + bias ----
        int colb = kt * KT + 2 * tg;
#pragma unroll
        for (int j = 0; j < 8; j++) {
            int col = colb + 8 * j;
            int d0 = qrow0 - col, d1 = qrow1 - col;
            sc[j][0] = sc[j][0] * 0.125f + bias_s[max(d0, 0)];
            sc[j][1] = sc[j][1] * 0.125f + bias_s[max(d0 - 1, 0)];
            sc[j][2] = sc[j][2] * 0.125f + bias_s[max(d1, 0)];
            sc[j][3] = sc[j][3] * 0.125f + bias_s[max(d1 - 1, 0)];
        }

        // ---- online softmax ----
        float mt0 = sc[0][0], mt1 = sc[0][2];
#pragma unroll
        for (int j = 0; j < 8; j++) {
            mt0 = fmaxf(mt0, fmaxf(sc[j][0], sc[j][1]));
            mt1 = fmaxf(mt1, fmaxf(sc[j][2], sc[j][3]));
        }
        mt0 = fmaxf(mt0, __shfl_xor_sync(0xffffffffu, mt0, 1));
        mt0 = fmaxf(mt0, __shfl_xor_sync(0xffffffffu, mt0, 2));
        mt1 = fmaxf(mt1, __shfl_xor_sync(0xffffffffu, mt1, 1));
        mt1 = fmaxf(mt1, __shfl_xor_sync(0xffffffffu, mt1, 2));
        float mn0 = fmaxf(m0, mt0), mn1 = fmaxf(m1, mt1);
        float cr0 = __expf(m0 - mn0), cr1 = __expf(m1 - mn1);
        float ps0 = 0.f, ps1 = 0.f;
#pragma unroll
        for (int j = 0; j < 8; j++) {
            sc[j][0] = __expf(sc[j][0] - mn0);
            sc[j][1] = __expf(sc[j][1] - mn0);
            sc[j][2] = __expf(sc[j][2] - mn1);
            sc[j][3] = __expf(sc[j][3] - mn1);
            ps0 += sc[j][0] + sc[j][1];
            ps1 += sc[j][2] + sc[j][3];
        }
        ps0 += __shfl_xor_sync(0xffffffffu, ps0, 1);
        ps0 += __shfl_xor_sync(0xffffffffu, ps0, 2);
        ps1 += __shfl_xor_sync(0xffffffffu, ps1, 1);
        ps1 += __shfl_xor_sync(0xffffffffu, ps1, 2);
        l0 = l0 * cr0 + ps0;  m0 = mn0;
        l1 = l1 * cr1 + ps1;  m1 = mn1;
#pragma unroll
        for (int j = 0; j < 8; j++) {
            acc[j][0] *= cr0; acc[j][1] *= cr0;
            acc[j][2] *= cr1; acc[j][3] *= cr1;
        }

        // ---- P -> fp16 hi/lo fragments ----
        uint32_t ph[8], ph2[8], pl[8], pl2[8];
#pragma unroll
        for (int j = 0; j < 8; j++) {
            ph[j]  = pack_f16x2(sc[j][0], sc[j][1]);
            pl[j]  = pack_resid_f16(sc[j][0], sc[j][1], ph[j]);
            ph2[j] = pack_f16x2(sc[j][2], sc[j][3]);
            pl2[j] = pack_resid_f16(sc[j][2], sc[j][3], ph2[j]);
        }

        // ---- O += P V (2-term) ----
#pragma unroll
        for (int j = 0; j < 8; j++) {
            uint32_t vbase = stg + KV_TILE + j * (8 * PITCH) + kv_off;
            uint32_t vh[8];
            ldsm_x4(&vh[0], vbase);
            ldsm_x4(&vh[4], vbase + 64);
#pragma unroll
            for (int s = 0; s < 4; s++) {
                uint32_t pA[4] = { ph[2*s], ph2[2*s], ph[2*s+1], ph2[2*s+1] };
                uint32_t pL[4] = { pl[2*s], pl2[2*s], pl[2*s+1], pl2[2*s+1] };
                mma_f16(acc[j], pA, &vh[2 * s]);
                mma_f16(acc[j], pL, &vh[2 * s]);
            }
        }
    }

    // ---- epilogue: normalize, write ctx split ----
    float inv0 = 1.f / l0, inv1 = 1.f / l1;
#pragma unroll
    for (int j = 0; j < 8; j++) {
        int e = h * 64 + 8 * j + 2 * tg;
        {
            float ox = acc[j][0] * inv0, oy = acc[j][1] * inv0;
            uint32_t hp = pack_f16x2(ox, oy);
            uint32_t lp = pack_resid_f16(ox, oy, hp);
            size_t base = ((size_t)b * SS + qrow0) * EE + e;
            *(uint32_t*)(g_chi + base) = hp;
            *(uint32_t*)(g_clo + base) = lp;
        }
        {
            float ox = acc[j][2] * inv1, oy = acc[j][3] * inv1;
            uint32_t hp = pack_f16x2(ox, oy);
            uint32_t lp = pack_resid_f16(ox, oy, hp);
            size_t base = ((size_t)b * SS + qrow1) * EE + e;
            *(uint32_t*)(g_chi + base) = hp;
            *(uint32_t*)(g_clo + base) = lp;
        }
    }
}

// ---------------------------------------------------------------------------
// Launcher
// ---------------------------------------------------------------------------
extern "C" void kernel_launch(void* const* d_in, const int* in_sizes, int n_in,
                              void* d_out, int out_size) {
    const float* hs  = (const float*)d_in[0];
    const float* Wq  = (const float*)d_in[1];
    const float* bq  = (const float*)d_in[2];
    const float* Wk  = (const float*)d_in[3];
    const float* bk  = (const float*)d_in[4];
    const float* Wv  = (const float*)d_in[5];
    const float* bv  = (const float*)d_in[6];
    const float* Wo  = (const float*)d_in[7];
    const float* bo  = (const float*)d_in[8];
    const float* rel = (const float*)d_in[9];
    float* out = (float*)d_out;

    cudaFuncSetAttribute(gemm_mma, cudaFuncAttributeMaxDynamicSharedMemorySize, GSMEM);
    cudaFuncSetAttribute(attn_tc, cudaFuncAttributeMaxDynamicSharedMemorySize, ATTN_SMEM);

    bias_kernel<<<(HH * SS + 255) / 256, 256>>>(rel);
    split_kernel<<<(MTOT * EE / 4 + 255) / 256, 256>>>(hs);
    dim3 wgrid(32, 32, 4), wblk(32, 8);
    wt_hi_kernel<<<wgrid, wblk>>>(Wq, Wk, Wv, Wo);

    // fused QKV (N = 3072)
    dim3 qkvgrid(24, MTOT / BM);      // (24, 32)
    gemm_mma<<<qkvgrid, 512, GSMEM>>>(bq, bk, bv, out, 1);

    dim3 agrid(SS / QT, HH, BB);      // (16, 16, 2)
    attn_tc<<<agrid, 256, ATTN_SMEM>>>();

    // O projection
    dim3 ogrid(EE / BN, MTOT / BM);   // (8, 32)
    gemm_mma<<<ogrid, 512, GSMEM>>>(bo, bo, bo, out, 0);
}

// round 8
// speedup vs baseline: 1.7409x; 1.0089x over previous
#include <cuda_runtime.h>
#include <cuda_fp16.h>
#include <stdint.h>
#include <math.h>

#define BB 2
#define SS 2048
#define EE 1024
#define HH 16
#define DD 64
#define MTOT (BB*SS)

// ---------------------------------------------------------------------------
// Scratch (device globals — no allocation allowed)
// ---------------------------------------------------------------------------
__device__ float g_bias8[HH*SS];
__device__ __half g_ahi[MTOT*EE], g_alo[MTOT*EE];      // hs 2-term split
__device__ __half g_wthi[4u*EE*EE];                    // W^T fp16 (q,k,v,o)
__device__ __half g_chi[MTOT*EE], g_clo[MTOT*EE];      // ctx 2-term split
__device__ __half g_qhi[BB*HH*SS*DD], g_qlo[BB*HH*SS*DD];  // [b][h][s][d] (unscaled)
__device__ __half g_khi[BB*HH*SS*DD];                      // [b][h][s][d]
__device__ __half g_vthi[BB*HH*SS*DD];                     // [b][h][d][s]

// ---------------------------------------------------------------------------
// helpers
// ---------------------------------------------------------------------------
__device__ __forceinline__ uint32_t smem_u32(const void* p) {
    uint32_t r;
    asm("{ .reg .u64 t; cvta.to.shared.u64 t, %1; cvt.u32.u64 %0, t; }"
        : "=r"(r) : "l"(p));
    return r;
}

__device__ __forceinline__ void cp16(uint32_t dst, const void* src) {
    asm volatile("cp.async.cg.shared.global [%0], [%1], 16;"
                 :: "r"(dst), "l"(__cvta_generic_to_global(src)) : "memory");
}

__device__ __forceinline__ void mma_f16(float* c, const uint32_t* a, const uint32_t* b) {
    asm volatile(
        "mma.sync.aligned.m16n8k16.row.col.f32.f16.f16.f32 "
        "{%0,%1,%2,%3}, {%4,%5,%6,%7}, {%8,%9}, {%0,%1,%2,%3};"
        : "+f"(c[0]), "+f"(c[1]), "+f"(c[2]), "+f"(c[3])
        : "r"(a[0]), "r"(a[1]), "r"(a[2]), "r"(a[3]), "r"(b[0]), "r"(b[1]));
}

__device__ __forceinline__ void ldsm_x4(uint32_t* r, uint32_t addr) {
    asm volatile("ldmatrix.sync.aligned.m8n8.x4.shared.b16 {%0,%1,%2,%3}, [%4];"
        : "=r"(r[0]), "=r"(r[1]), "=r"(r[2]), "=r"(r[3]) : "r"(addr));
}

__device__ __forceinline__ uint32_t pack_f16x2(float a, float b) {
    uint32_t d;
    asm("cvt.rn.f16x2.f32 %0, %1, %2;" : "=r"(d) : "f"(b), "f"(a));
    return d;
}
__device__ __forceinline__ uint32_t pack_resid_f16(float a, float b, uint32_t hi) {
    __half2 h = *reinterpret_cast<__half2*>(&hi);
    float2 f = __half22float2(h);
    return pack_f16x2(a - f.x, b - f.y);
}

// ---------------------------------------------------------------------------
// bias table
// ---------------------------------------------------------------------------
__global__ void bias_kernel(const float* __restrict__ rel_bias) {
    int idx = blockIdx.x * blockDim.x + threadIdx.x;
    if (idx >= HH * SS) return;
    int h = idx / SS;
    int d = idx % SS;
    int bucket;
    if (d < 16) {
        bucket = d;
    } else {
        float t = (logf((float)d * 0.0625f) / 1.3862943611198906f) * 16.0f;
        int lb = 16 + (int)t;
        bucket = lb < 31 ? lb : 31;
    }
    g_bias8[idx] = rel_bias[bucket * HH + h] * 8.0f;
}

// ---------------------------------------------------------------------------
// split fp32 -> fp16 hi/lo for hs
// ---------------------------------------------------------------------------
__global__ void split_kernel(const float* __restrict__ in) {
    int i = blockIdx.x * blockDim.x + threadIdx.x;
    if (i >= MTOT * EE / 4) return;
    float4 v = ((const float4*)in)[i];
    uint32_t h01 = pack_f16x2(v.x, v.y), h23 = pack_f16x2(v.z, v.w);
    uint32_t l01 = pack_resid_f16(v.x, v.y, h01), l23 = pack_resid_f16(v.z, v.w, h23);
    ((uint32_t*)g_ahi)[i * 2] = h01;  ((uint32_t*)g_ahi)[i * 2 + 1] = h23;
    ((uint32_t*)g_alo)[i * 2] = l01;  ((uint32_t*)g_alo)[i * 2 + 1] = l23;
}

// ---------------------------------------------------------------------------
// transpose weights -> fp16 [N][K]
// ---------------------------------------------------------------------------
__global__ void wt_hi_kernel(const float* __restrict__ W0, const float* __restrict__ W1,
                             const float* __restrict__ W2, const float* __restrict__ W3) {
    __shared__ float t[32][33];
    int widx = blockIdx.z;
    const float* W = (widx == 0) ? W0 : (widx == 1) ? W1 : (widx == 2) ? W2 : W3;
    int n0 = blockIdx.x * 32, k0 = blockIdx.y * 32;
    int tx = threadIdx.x, ty = threadIdx.y;
#pragma unroll
    for (int i = 0; i < 4; i++)
        t[ty + i * 8][tx] = W[(size_t)(k0 + ty + i * 8) * EE + n0 + tx];
    __syncthreads();
    __half* hi = g_wthi + (size_t)widx * EE * EE;
#pragma unroll
    for (int i = 0; i < 4; i++) {
        int n = n0 + ty + i * 8, k = k0 + tx;
        hi[(size_t)n * EE + k] = __float2half(t[tx][ty + i * 8]);
    }
}

// ---------------------------------------------------------------------------
// mma.sync fp16 2-term GEMM, 512 threads / 16 warps (4m x 4n), warp tile 32x32
//   BK=64 per stage, 3-stage ring, 16 iterations
//   mode 1: fused QKV (grid.x = 24), mode 0: O-proj (grid.x = 8)
// ---------------------------------------------------------------------------
#define BM 128
#define BN 128
#define BK 64
#define NSTAGE 3
#define RPADG 144
#define GTILE (128 * RPADG)            // 18432
#define STAGE_BYTES (3 * GTILE)        // 55296 {Ahi, Alo, B}
#define GSMEM (NSTAGE * STAGE_BYTES)   // 165888
#define NITER 16

__global__ __launch_bounds__(512, 1)
void gemm_mma(const float* __restrict__ b0, const float* __restrict__ b1,
              const float* __restrict__ b2, float* __restrict__ outp, int mode) {
    extern __shared__ char sm[];
    int tid = threadIdx.x;
    int lane = tid & 31, wid = tid >> 5;
    int wm = wid & 3, wn = wid >> 2;           // 4 m-warps x 4 n-warps
    int g = lane >> 2, tg = lane & 3;
    int m0 = blockIdx.y * BM;

    int widx, n0;
    if (mode == 0) { widx = 3; n0 = blockIdx.x * BN; }
    else { widx = blockIdx.x >> 3; n0 = (blockIdx.x & 7) * BN; }

    const float* bias = (mode == 0) ? b0 : (widx == 0) ? b0 : (widx == 1) ? b1 : b2;
    const __half* Ahi = (mode == 0) ? g_chi : g_ahi;
    const __half* Alo = (mode == 0) ? g_clo : g_alo;
    const __half* Bhi = g_wthi + (size_t)widx * EE * EE;

    float c[2][4][4];
#pragma unroll
    for (int mt = 0; mt < 2; mt++)
#pragma unroll
        for (int nt = 0; nt < 4; nt++)
#pragma unroll
            for (int i = 0; i < 4; i++) c[mt][nt][i] = 0.f;

    uint32_t smbase = smem_u32(sm);
    uint32_t a_lrow = ((uint32_t)((lane >> 3) & 1)) * 8 + (lane & 7);
    uint32_t a_lcol = ((uint32_t)(lane >> 4)) * 16;
    uint32_t b_lrow = lane & 7;
    uint32_t b_lcol = ((uint32_t)(lane >> 3)) * 16;

    auto load_stage = [&](int git, int s) {
        int kb = git * BK;
        uint32_t st = smbase + s * STAGE_BYTES;
#pragma unroll
        for (int i = 0; i < 2; i++) {
            int ch = tid + i * 512;            // 0..1023
            int m = ch >> 3, lk = ch & 7;
            uint32_t off = m * RPADG + lk * 16;
            size_t ga = (size_t)(m0 + m) * EE + kb + lk * 8;
            cp16(st + off,             Ahi + ga);
            cp16(st + GTILE + off,     Alo + ga);
            cp16(st + 2 * GTILE + off, Bhi + (size_t)(n0 + m) * EE + kb + lk * 8);
        }
    };

    load_stage(0, 0);
    asm volatile("cp.async.commit_group;" ::: "memory");
    load_stage(1, 1);
    asm volatile("cp.async.commit_group;" ::: "memory");

    for (int git = 0; git < NITER; git++) {
        asm volatile("cp.async.wait_group 1;" ::: "memory");
        __syncthreads();

        if (git + 2 < NITER) load_stage(git + 2, (git + 2) % 3);
        asm volatile("cp.async.commit_group;" ::: "memory");

        uint32_t st = smbase + (git % 3) * STAGE_BYTES;
        uint32_t Bs = st + 2 * GTILE;

        uint32_t b[4][8];
#pragma unroll
        for (int nt = 0; nt < 4; nt++) {
            uint32_t base = Bs + (wn * 32 + nt * 8 + b_lrow) * RPADG + b_lcol;
            ldsm_x4(&b[nt][0], base);
            ldsm_x4(&b[nt][4], base + 64);
        }

#pragma unroll
        for (int seg = 0; seg < 2; seg++) {
            uint32_t As = st + seg * GTILE;
            uint32_t a[2][16];
#pragma unroll
            for (int mt = 0; mt < 2; mt++)
#pragma unroll
                for (int ks = 0; ks < 4; ks++)
                    ldsm_x4(&a[mt][ks * 4],
                            As + (wm * 32 + mt * 16 + a_lrow) * RPADG + ks * 32 + a_lcol);
#pragma unroll
            for (int ks = 0; ks < 4; ks++)
#pragma unroll
                for (int mt = 0; mt < 2; mt++)
#pragma unroll
                    for (int nt = 0; nt < 4; nt++)
                        mma_f16(c[mt][nt], &a[mt][ks * 4], &b[nt][ks * 2]);
        }
    }

    // epilogue
#pragma unroll
    for (int mt = 0; mt < 2; mt++) {
#pragma unroll
        for (int nt = 0; nt < 4; nt++) {
            int n = n0 + wn * 32 + nt * 8 + 2 * tg;
            float bx = bias[n], by = bias[n + 1];
#pragma unroll
            for (int hh = 0; hh < 2; hh++) {
                int r = m0 + wm * 32 + mt * 16 + g + hh * 8;
                float vx = c[mt][nt][2 * hh] + bx;
                float vy = c[mt][nt][2 * hh + 1] + by;
                if (mode == 0) {
                    *(float2*)(outp + (size_t)r * EE + n) = make_float2(vx, vy);
                } else {
                    uint32_t hp = pack_f16x2(vx, vy);
                    int head = n >> 6, d = n & 63;
                    int bidx = r >> 11, srow = r & 2047;
                    size_t bh = (size_t)bidx * HH + head;
                    if (widx == 2) {
                        size_t i0 = (bh * DD + d) * SS + srow;
                        size_t i1 = (bh * DD + d + 1) * SS + srow;
                        g_vthi[i0] = __ushort_as_half((unsigned short)(hp & 0xffff));
                        g_vthi[i1] = __ushort_as_half((unsigned short)(hp >> 16));
                    } else if (widx == 1) {
                        *(uint32_t*)(g_khi + (bh * SS + srow) * DD + d) = hp;
                    } else {
                        uint32_t lp = pack_resid_f16(vx, vy, hp);
                        size_t idx = (bh * SS + srow) * DD + d;
                        *(uint32_t*)(g_qhi + idx) = hp;
                        *(uint32_t*)(g_qlo + idx) = lp;
                    }
                }
            }
        }
    }
}

// ---------------------------------------------------------------------------
// tensor-core flash attention, fp16 2-term, 3-stage KV ring, 1 sync/iter
// ---------------------------------------------------------------------------
#define QT 128
#define KT 64
#define PITCH 144
#define KV_TILE (KT * PITCH)
#define KV_STAGE (2 * KV_TILE)
#define OFF_QHI 8192
#define OFF_QLO (OFF_QHI + QT * PITCH)
#define OFF_ST  (OFF_QLO + QT * PITCH)
#define ATTN_SMEM (OFF_ST + 3 * KV_STAGE)

__global__ __launch_bounds__(256, 1)
void attn_tc() {
    extern __shared__ char sm[];
    float* bias_s = (float*)sm;
    uint32_t smb = smem_u32(sm);
    int tid = threadIdx.x, lane = tid & 31, w = tid >> 5;
    int g = lane >> 2, tg = lane & 3;
    int qt = blockIdx.x, h = blockIdx.y, b = blockIdx.z;
    int q0 = qt * QT;
    size_t bh = (size_t)b * HH + h;

    const __half* Khi = g_khi + bh * SS * DD;
    const __half* Vhi = g_vthi + bh * DD * SS;
    const __half* Qhi = g_qhi + (bh * SS + q0) * DD;
    const __half* Qlo = g_qlo + (bh * SS + q0) * DD;

    const float4* br = (const float4*)(g_bias8 + h * SS);
    for (int i = tid; i < SS / 4; i += 256) ((float4*)bias_s)[i] = br[i];

    auto load_kv = [&](int kt, int s) {
        uint32_t base = smb + OFF_ST + s * KV_STAGE;
        int k0 = kt * KT;
#pragma unroll
        for (int i = 0; i < 2; i++) {
            int ch = tid + i * 256;
            int r = ch >> 3, cc = ch & 7;
            uint32_t off = r * PITCH + cc * 16;
            cp16(base + off,           Khi + (size_t)(k0 + r) * 64 + cc * 8);
            cp16(base + KV_TILE + off, Vhi + (size_t)r * SS + k0 + cc * 8);
        }
    };

#pragma unroll
    for (int i = 0; i < 4; i++) {
        int ch = tid + i * 256;
        int r = ch >> 3, cc = ch & 7;
        uint32_t off = r * PITCH + cc * 16;
        cp16(smb + OFF_QHI + off, Qhi + r * 64 + cc * 8);
        cp16(smb + OFF_QLO + off, Qlo + r * 64 + cc * 8);
    }
    load_kv(0, 0);
    asm volatile("cp.async.commit_group;" ::: "memory");
    load_kv(1, 1);
    asm volatile("cp.async.commit_group;" ::: "memory");

    float m0 = -1e30f, m1 = -1e30f, l0 = 0.f, l1 = 0.f;
    float acc[8][4];
#pragma unroll
    for (int j = 0; j < 8; j++)
#pragma unroll
        for (int i = 0; i < 4; i++) acc[j][i] = 0.f;

    uint32_t qh[16], ql[16];
    int qrow0 = q0 + w * 16 + g;
    int qrow1 = qrow0 + 8;

    uint32_t a_lrow = ((uint32_t)((lane >> 3) & 1)) * 8 + (lane & 7);
    uint32_t a_lcol = ((uint32_t)(lane >> 4)) * 16;
    uint32_t kv_off = (lane & 7) * PITCH + ((uint32_t)(lane >> 3)) * 16;

    for (int kt = 0; kt < 32; kt++) {
        asm volatile("cp.async.wait_group 1;" ::: "memory");
        __syncthreads();

        if (kt + 2 < 32) load_kv(kt + 2, (kt + 2) % 3);
        asm volatile("cp.async.commit_group;" ::: "memory");

        if (kt == 0) {
#pragma unroll
            for (int s = 0; s < 4; s++) {
                uint32_t base = smb + OFF_QHI + (w * 16 + a_lrow) * PITCH + s * 32 + a_lcol;
                ldsm_x4(&qh[4 * s], base);
                ldsm_x4(&ql[4 * s], base + (OFF_QLO - OFF_QHI));
            }
        }

        uint32_t stg = smb + OFF_ST + (kt % 3) * KV_STAGE;

        // ---- S = Q K^T (2-term) ----
        float sc[8][4];
#pragma unroll
        for (int j = 0; j < 8; j++) {
#pragma unroll
            for (int i = 0; i < 4; i++) sc[j][i] = 0.f;
            uint32_t kbase = stg + j * (8 * PITCH) + kv_off;
            uint32_t kh[8];
            ldsm_x4(&kh[0], kbase);
            ldsm_x4(&kh[4], kbase + 64);
#pragma unroll
            for (int s = 0; s < 4; s++) {
                mma_f16(sc[j], &qh[4 * s], &kh[2 * s]);
                mma_f16(sc[j], &ql[4 * s], &kh[2 * s]);
            }
        }

        // ---- scale + bias ----
        int colb = kt * KT + 2 * tg;
#pragma unroll
        for (int j = 0; j < 8; j++) {
            int col = colb + 8 * j;
            int d0 = qrow0 - col, d1 = qrow1 - col;
            sc[j][0] = sc[j][0] * 0.125f + bias_s[max(d0, 0)];
            sc[j][1] = sc[j][1] * 0.125f + bias_s[max(d0 - 1, 0)];
            sc[j][2] = sc[j][2] * 0.125f + bias_s[max(d1, 0)];
            sc[j][3] = sc[j][3] * 0.125f + bias_s[max(d1 - 1, 0)];
        }

        // ---- online softmax ----
        float mt0 = sc[0][0], mt1 = sc[0][2];
#pragma unroll
        for (int j = 0; j < 8; j++) {
            mt0 = fmaxf(mt0, fmaxf(sc[j][0], sc[j][1]));
            mt1 = fmaxf(mt1, fmaxf(sc[j][2], sc[j][3]));
        }
        mt0 = fmaxf(mt0, __shfl_xor_sync(0xffffffffu, mt0, 1));
        mt0 = fmaxf(mt0, __shfl_xor_sync(0xffffffffu, mt0, 2));
        mt1 = fmaxf(mt1, __shfl_xor_sync(0xffffffffu, mt1, 1));
        mt1 = fmaxf(mt1, __shfl_xor_sync(0xffffffffu, mt1, 2));
        float mn0 = fmaxf(m0, mt0), mn1 = fmaxf(m1, mt1);
        float cr0 = __expf(m0 - mn0), cr1 = __expf(m1 - mn1);
        float ps0 = 0.f, ps1 = 0.f;
#pragma unroll
        for (int j = 0; j < 8; j++) {
            sc[j][0] = __expf(sc[j][0] - mn0);
            sc[j][1] = __expf(sc[j][1] - mn0);
            sc[j][2] = __expf(sc[j][2] - mn1);
            sc[j][3] = __expf(sc[j][3] - mn1);
            ps0 += sc[j][0] + sc[j][1];
            ps1 += sc[j][2] + sc[j][3];
        }
        ps0 += __shfl_xor_sync(0xffffffffu, ps0, 1);
        ps0 += __shfl_xor_sync(0xffffffffu, ps0, 2);
        ps1 += __shfl_xor_sync(0xffffffffu, ps1, 1);
        ps1 += __shfl_xor_sync(0xffffffffu, ps1, 2);
        l0 = l0 * cr0 + ps0;  m0 = mn0;
        l1 = l1 * cr1 + ps1;  m1 = mn1;
#pragma unroll
        for (int j = 0; j < 8; j++) {
            acc[j][0] *= cr0; acc[j][1] *= cr0;
            acc[j][2] *= cr1; acc[j][3] *= cr1;
        }

        // ---- P -> fp16 hi/lo fragments ----
        uint32_t ph[8], ph2[8], pl[8], pl2[8];
#pragma unroll
        for (int j = 0; j < 8; j++) {
            ph[j]  = pack_f16x2(sc[j][0], sc[j][1]);
            pl[j]  = pack_resid_f16(sc[j][0], sc[j][1], ph[j]);
            ph2[j] = pack_f16x2(sc[j][2], sc[j][3]);
            pl2[j] = pack_resid_f16(sc[j][2], sc[j][3], ph2[j]);
        }

        // ---- O += P V (2-term) ----
#pragma unroll
        for (int j = 0; j < 8; j++) {
            uint32_t vbase = stg + KV_TILE + j * (8 * PITCH) + kv_off;
            uint32_t vh[8];
            ldsm_x4(&vh[0], vbase);
            ldsm_x4(&vh[4], vbase + 64);
#pragma unroll
            for (int s = 0; s < 4; s++) {
                uint32_t pA[4] = { ph[2*s], ph2[2*s], ph[2*s+1], ph2[2*s+1] };
                uint32_t pL[4] = { pl[2*s], pl2[2*s], pl[2*s+1], pl2[2*s+1] };
                mma_f16(acc[j], pA, &vh[2 * s]);
                mma_f16(acc[j], pL, &vh[2 * s]);
            }
        }
    }

    // ---- epilogue: normalize, write ctx split ----
    float inv0 = 1.f / l0, inv1 = 1.f / l1;
#pragma unroll
    for (int j = 0; j < 8; j++) {
        int e = h * 64 + 8 * j + 2 * tg;
        {
            float ox = acc[j][0] * inv0, oy = acc[j][1] * inv0;
            uint32_t hp = pack_f16x2(ox, oy);
            uint32_t lp = pack_resid_f16(ox, oy, hp);
            size_t base = ((size_t)b * SS + qrow0) * EE + e;
            *(uint32_t*)(g_chi + base) = hp;
            *(uint32_t*)(g_clo + base) = lp;
        }
        {
            float ox = acc[j][2] * inv1, oy = acc[j][3] * inv1;
            uint32_t hp = pack_f16x2(ox, oy);
            uint32_t lp = pack_resid_f16(ox, oy, hp);
            size_t base = ((size_t)b * SS + qrow1) * EE + e;
            *(uint32_t*)(g_chi + base) = hp;
            *(uint32_t*)(g_clo + base) = lp;
        }
    }
}

// ---------------------------------------------------------------------------
// Launcher
// ---------------------------------------------------------------------------
extern "C" void kernel_launch(void* const* d_in, const int* in_sizes, int n_in,
                              void* d_out, int out_size) {
    const float* hs  = (const float*)d_in[0];
    const float* Wq  = (const float*)d_in[1];
    const float* bq  = (const float*)d_in[2];
    const float* Wk  = (const float*)d_in[3];
    const float* bk  = (const float*)d_in[4];
    const float* Wv  = (const float*)d_in[5];
    const float* bv  = (const float*)d_in[6];
    const float* Wo  = (const float*)d_in[7];
    const float* bo  = (const float*)d_in[8];
    const float* rel = (const float*)d_in[9];
    float* out = (float*)d_out;

    cudaFuncSetAttribute(gemm_mma, cudaFuncAttributeMaxDynamicSharedMemorySize, GSMEM);
    cudaFuncSetAttribute(attn_tc, cudaFuncAttributeMaxDynamicSharedMemorySize, ATTN_SMEM);

    bias_kernel<<<(HH * SS + 255) / 256, 256>>>(rel);
    split_kernel<<<(MTOT * EE / 4 + 255) / 256, 256>>>(hs);
    dim3 wgrid(32, 32, 4), wblk(32, 8);
    wt_hi_kernel<<<wgrid, wblk>>>(Wq, Wk, Wv, Wo);

    // fused QKV (N = 3072)
    dim3 qkvgrid(24, MTOT / BM);      // (24, 32)
    gemm_mma<<<qkvgrid, 512, GSMEM>>>(bq, bk, bv, out, 1);

    dim3 agrid(SS / QT, HH, BB);      // (16, 16, 2)
    attn_tc<<<agrid, 256, ATTN_SMEM>>>();

    // O projection
    dim3 ogrid(EE / BN, MTOT / BM);   // (8, 32)
    gemm_mma<<<ogrid, 512, GSMEM>>>(bo, bo, bo, out, 0);
}